// round 2
// baseline (speedup 1.0000x reference)
#include <cuda_runtime.h>
#include <cuda_bf16.h>
#include <cstdint>

#define NMAX 100000
#define D    128

// Scratch (allocation-free rule: __device__ globals)
__device__ __align__(16) float g_P[(size_t)NMAX * D];   // projected features (x@Wl)
__device__ __align__(16) float g_A[(size_t)NMAX * D];   // aggregated sums
__device__ __align__(16) float g_H[(size_t)NMAX * D];   // layer-1 output
__device__ int g_cnt[NMAX];
__device__ int g_is64;

typedef unsigned long long ull;

// edge_index dtype detection: reference asks for int64 but JAX (x64 disabled)
// typically yields int32. For int64 < 2^31 every odd 32-bit word is zero.
__global__ void detect_kernel(const int* __restrict__ ei32, int E) {
    if (blockIdx.x == 0 && threadIdx.x == 0) {
        int m = E < 64 ? E : 64;
        int is64 = 1;
        for (int i = 0; i < m; i++)
            if (ei32[2 * i + 1] != 0) { is64 = 0; break; }
        g_is64 = is64;
    }
}

__device__ __forceinline__ int get_idx(const void* __restrict__ ei, int is64, long long elem) {
    if (is64) return (int)((const long long*)ei)[elem];
    return ((const int*)ei)[elem];
}

__device__ __forceinline__ ull pk2(float v) {
    ull r;
    asm("mov.b64 %0, {%1, %1};" : "=l"(r) : "f"(v));
    return r;
}
__device__ __forceinline__ void fma2(ull& d, ull a, ull b) {
    asm("fma.rn.f32x2 %0, %1, %2, %0;" : "+l"(d) : "l"(a), "l"(b));
}
__device__ __forceinline__ float2 up2(ull u) {
    float2 r;
    asm("mov.b64 {%0, %1}, %2;" : "=f"(r.x), "=f"(r.y) : "l"(u));
    return r;
}

// ---------------------------------------------------------------------------
// zero A (+ cnt)
// ---------------------------------------------------------------------------
__global__ void zero_all_kernel(int n, int with_cnt) {
    int total4 = n * (D / 4);
    int stride = gridDim.x * blockDim.x;
    float4 z = make_float4(0.f, 0.f, 0.f, 0.f);
    for (int i = blockIdx.x * blockDim.x + threadIdx.x; i < total4; i += stride)
        ((float4*)g_A)[i] = z;
    if (with_cnt) {
        for (int i = blockIdx.x * blockDim.x + threadIdx.x; i < n; i += stride)
            g_cnt[i] = 0;
    }
}

// ---------------------------------------------------------------------------
// degree histogram
// ---------------------------------------------------------------------------
__global__ void count_kernel(const void* __restrict__ ei, int E) {
    int e = blockIdx.x * blockDim.x + threadIdx.x;
    int is64 = g_is64;
    if (e < E) {
        int d = get_idx(ei, is64, (long long)E + e);   // dst row
        atomicAdd(&g_cnt[d], 1);
    }
}

// ---------------------------------------------------------------------------
// scatter-add of projected rows: A[dst] += P[src]  (one warp per edge)
// ---------------------------------------------------------------------------
__global__ void scatter_kernel(const void* __restrict__ ei,
                               const float* __restrict__ P,
                               float* __restrict__ A, int E) {
    int g = blockIdx.x * blockDim.x + threadIdx.x;
    int e = g >> 5;
    int lane = g & 31;
    if (e >= E) return;
    int is64 = g_is64;
    int s = get_idx(ei, is64, e);                     // src row
    int d = get_idx(ei, is64, (long long)E + e);      // dst row
    float4 v = ((const float4*)(P + (size_t)s * D))[lane];
    float* p = A + (size_t)d * D + lane * 4;
    asm volatile("red.global.add.v4.f32 [%0], {%1,%2,%3,%4};"
                 :: "l"(p), "f"(v.x), "f"(v.y), "f"(v.z), "f"(v.w) : "memory");
}

// ---------------------------------------------------------------------------
// GEMM  out[n,128] = X[n,128] @ W[128,128]  (+ optional epilogue)
// EPI 0: out = acc                  (write projected features)
// EPI 1: out = relu(acc + Agg*inv + bias)
// EPI 2: out =      acc + Agg*inv + bias
// fp32 via packed fma.rn.f32x2 (FFMA2), 128x128 tile, 256 threads, 8x8/thread
// ---------------------------------------------------------------------------
#define BM 128
#define PADM 132
#define SMEM_BYTES ((BM * PADM + D * D) * 4)

template <int EPI>
__global__ void __launch_bounds__(256, 1)
gemm_kernel(const float* __restrict__ X, const float* __restrict__ W,
            const float* __restrict__ bias, const float* __restrict__ Agg,
            const int* __restrict__ cnt, float* __restrict__ out, int nrows) {
    extern __shared__ float sm[];
    float* Xs = sm;                 // [128][132]  row-major, padded
    float* Ws = sm + BM * PADM;     // [128][128]  row-major (k, c)

    int tid = threadIdx.x;
    int rowbase = blockIdx.x * BM;

    // --- load tiles (both are contiguous 128x128 fp32 blocks) ---
    {
        const float4* Xg = (const float4*)(X + (size_t)rowbase * D);
        float4 z = make_float4(0.f, 0.f, 0.f, 0.f);
#pragma unroll
        for (int i = 0; i < 16; i++) {
            int f = tid + i * 256;        // float4 index within tile
            int m = f >> 5;               // 32 float4 per row
            int kk = (f & 31) << 2;
            float4 v = (rowbase + m < nrows) ? Xg[f] : z;
            *(float4*)(Xs + m * PADM + kk) = v;
        }
        const float4* Wg = (const float4*)W;
        float4* Ws4 = (float4*)Ws;
#pragma unroll
        for (int i = 0; i < 16; i++) Ws4[tid + i * 256] = Wg[tid + i * 256];
    }
    __syncthreads();

    int tr = tid >> 4;            // 0..15 -> rows tr*8..tr*8+7
    int tc = tid & 15;            // 0..15 -> cols tc*8..tc*8+7
    int r0 = tr * 8, c0 = tc * 8;

    ull acc[8][4];
#pragma unroll
    for (int i = 0; i < 8; i++)
#pragma unroll
        for (int j = 0; j < 4; j++) acc[i][j] = 0ull;

    const ulonglong2* W2p = (const ulonglong2*)Ws;
#pragma unroll 4
    for (int k = 0; k < D; k++) {
        ull aa[8];
#pragma unroll
        for (int i = 0; i < 8; i++) aa[i] = pk2(Xs[(r0 + i) * PADM + k]);
        ulonglong2 p = W2p[k * 32 + tc * 2];
        ulonglong2 q = W2p[k * 32 + tc * 2 + 1];
        ull b[4] = {p.x, p.y, q.x, q.y};
#pragma unroll
        for (int i = 0; i < 8; i++)
#pragma unroll
            for (int j = 0; j < 4; j++) fma2(acc[i][j], aa[i], b[j]);
    }

    // --- epilogue ---
#pragma unroll
    for (int i = 0; i < 8; i++) {
        int r = rowbase + r0 + i;
        if (r >= nrows) continue;
        float2 v0 = up2(acc[i][0]), v1 = up2(acc[i][1]);
        float2 v2 = up2(acc[i][2]), v3 = up2(acc[i][3]);
        float res[8] = {v0.x, v0.y, v1.x, v1.y, v2.x, v2.y, v3.x, v3.y};
        if (EPI != 0) {
            float inv = 1.0f / fmaxf((float)cnt[r], 1.0f);
            const float4* ag = (const float4*)(Agg + (size_t)r * D + c0);
            float4 a0 = ag[0], a1 = ag[1];
            const float4* bp = (const float4*)(bias + c0);
            float4 bv0 = bp[0], bv1 = bp[1];
            res[0] += a0.x * inv + bv0.x;
            res[1] += a0.y * inv + bv0.y;
            res[2] += a0.z * inv + bv0.z;
            res[3] += a0.w * inv + bv0.w;
            res[4] += a1.x * inv + bv1.x;
            res[5] += a1.y * inv + bv1.y;
            res[6] += a1.z * inv + bv1.z;
            res[7] += a1.w * inv + bv1.w;
            if (EPI == 1) {
#pragma unroll
                for (int j = 0; j < 8; j++) res[j] = fmaxf(res[j], 0.0f);
            }
        }
        float4* op = (float4*)(out + (size_t)r * D + c0);
        op[0] = make_float4(res[0], res[1], res[2], res[3]);
        op[1] = make_float4(res[4], res[5], res[6], res[7]);
    }
}

// ---------------------------------------------------------------------------
extern "C" void kernel_launch(void* const* d_in, const int* in_sizes, int n_in,
                              void* d_out, int out_size) {
    const float* x   = (const float*)d_in[0];
    const void*  ei  = d_in[1];
    const float* W1l = (const float*)d_in[2];
    const float* b1  = (const float*)d_in[3];
    const float* W1r = (const float*)d_in[4];
    const float* W2l = (const float*)d_in[5];
    const float* b2  = (const float*)d_in[6];
    const float* W2r = (const float*)d_in[7];
    float* out = (float*)d_out;

    int n = in_sizes[0] / D;
    int E = in_sizes[1] / 2;

    float *P, *A, *H;
    int* cnt;
    cudaGetSymbolAddress((void**)&P, g_P);
    cudaGetSymbolAddress((void**)&A, g_A);
    cudaGetSymbolAddress((void**)&H, g_H);
    cudaGetSymbolAddress((void**)&cnt, g_cnt);

    cudaFuncSetAttribute(gemm_kernel<0>, cudaFuncAttributeMaxDynamicSharedMemorySize, SMEM_BYTES);
    cudaFuncSetAttribute(gemm_kernel<1>, cudaFuncAttributeMaxDynamicSharedMemorySize, SMEM_BYTES);
    cudaFuncSetAttribute(gemm_kernel<2>, cudaFuncAttributeMaxDynamicSharedMemorySize, SMEM_BYTES);

    int G = (n + BM - 1) / BM;
    int scatterBlocks = (E * 32 + 255) / 256;

    detect_kernel<<<1, 32>>>((const int*)ei, E);

    // layer 1
    zero_all_kernel<<<2048, 256>>>(n, 1);
    count_kernel<<<(E + 255) / 256, 256>>>(ei, E);
    gemm_kernel<0><<<G, 256, SMEM_BYTES>>>(x, W1l, nullptr, nullptr, nullptr, P, n);
    scatter_kernel<<<scatterBlocks, 256>>>(ei, P, A, E);
    gemm_kernel<1><<<G, 256, SMEM_BYTES>>>(x, W1r, b1, A, cnt, H, n);

    // layer 2
    zero_all_kernel<<<2048, 256>>>(n, 0);
    gemm_kernel<0><<<G, 256, SMEM_BYTES>>>(H, W2l, nullptr, nullptr, nullptr, P, n);
    scatter_kernel<<<scatterBlocks, 256>>>(ei, P, A, E);
    gemm_kernel<2><<<G, 256, SMEM_BYTES>>>(H, W2r, b2, A, cnt, out, n);
}

// round 4
// speedup vs baseline: 1.5979x; 1.5979x over previous
#include <cuda_runtime.h>
#include <cuda_bf16.h>
#include <cstdint>

#define NMAX 100000
#define EMAX 1700000
#define D    128

// Scratch (__device__ globals; allocation-free rule)
__device__ __align__(16) float g_P[(size_t)NMAX * D];   // X @ Wl
__device__ __align__(16) float g_R[(size_t)NMAX * D];   // X @ Wr
__device__ __align__(16) float g_H[(size_t)NMAX * D];   // layer-1 output
__device__ int g_cnt[NMAX];
__device__ int g_ptr[NMAX + 1];
__device__ int g_fill[NMAX];
__device__ int g_nbr[EMAX];
__device__ int g_bsum[256];
__device__ int g_boff[256];
__device__ int g_is64;

typedef unsigned long long ull;

__device__ __forceinline__ ull pk2(float v) {
    ull r; asm("mov.b64 %0, {%1, %1};" : "=l"(r) : "f"(v)); return r;
}
__device__ __forceinline__ void fma2(ull& d, ull a, ull b) {
    asm("fma.rn.f32x2 %0, %1, %2, %0;" : "+l"(d) : "l"(a), "l"(b));
}
__device__ __forceinline__ float2 up2(ull u) {
    float2 r; asm("mov.b64 {%0, %1}, %2;" : "=f"(r.x), "=f"(r.y) : "l"(u)); return r;
}

// ---- edge dtype detect: int64 < 2^31 -> odd 32-bit words all zero ----------
__global__ void detect_kernel(const int* __restrict__ ei32, int E) {
    if (threadIdx.x == 0) {
        int m = E < 64 ? E : 64;
        int is64 = 1;
        for (int i = 0; i < m; i++)
            if (ei32[2 * i + 1] != 0) { is64 = 0; break; }
        g_is64 = is64;
    }
}
__device__ __forceinline__ int get_idx(const void* __restrict__ ei, int is64, long long elem) {
    if (is64) return (int)((const long long*)ei)[elem];
    return ((const int*)ei)[elem];
}

// ---- CSR build --------------------------------------------------------------
__global__ void zero_cnt_kernel(int n) {
    for (int i = blockIdx.x * blockDim.x + threadIdx.x; i < n; i += gridDim.x * blockDim.x)
        g_cnt[i] = 0;
}
__global__ void count_kernel(const void* __restrict__ ei, int E) {
    int e = blockIdx.x * blockDim.x + threadIdx.x;
    int is64 = g_is64;
    if (e < E) atomicAdd(&g_cnt[get_idx(ei, is64, (long long)E + e)], 1);
}
// phase A: per-512-block exclusive scan of cnt -> ptr, block sums -> bsum
__global__ void scanA_kernel(int n) {
    __shared__ int s[512];
    int tid = threadIdx.x;
    int i = blockIdx.x * 512 + tid;
    int x = (i < n) ? g_cnt[i] : 0;
    s[tid] = x;
    __syncthreads();
    for (int off = 1; off < 512; off <<= 1) {
        int v = (tid >= off) ? s[tid - off] : 0;
        __syncthreads();
        s[tid] += v;
        __syncthreads();
    }
    if (i < n) g_ptr[i] = s[tid] - x;
    if (tid == 511) g_bsum[blockIdx.x] = s[tid];
}
// phase B: exclusive scan of block sums (single block; NB<=196<256)
__global__ void scanB_kernel(int nb) {
    __shared__ int s[256];
    int tid = threadIdx.x;
    int x = (tid < nb) ? g_bsum[tid] : 0;
    s[tid] = x;
    __syncthreads();
    for (int off = 1; off < 256; off <<= 1) {
        int v = (tid >= off) ? s[tid - off] : 0;
        __syncthreads();
        s[tid] += v;
        __syncthreads();
    }
    if (tid < nb) g_boff[tid] = s[tid] - x;
}
// phase C: add block offsets, init fill cursors, set ptr[n]=E
__global__ void scanC_kernel(int n, int E) {
    int i = blockIdx.x * blockDim.x + threadIdx.x;
    if (i < n) {
        int v = g_ptr[i] + g_boff[i >> 9];
        g_ptr[i] = v;
        g_fill[i] = v;
    }
    if (i == 0) g_ptr[n] = E;
}
__global__ void fill_kernel(const void* __restrict__ ei, int E) {
    int e = blockIdx.x * blockDim.x + threadIdx.x;
    int is64 = g_is64;
    if (e < E) {
        int s = get_idx(ei, is64, e);
        int d = get_idx(ei, is64, (long long)E + e);
        int pos = atomicAdd(&g_fill[d], 1);
        g_nbr[pos] = s;
    }
}

// ---------------------------------------------------------------------------
// GEMM  out[n,128] = X[n,128] @ W[128,128]   (plain, no epilogue)
// Full W in smem (64KB) + transposed X k-tile Xs[64][132] (33KB) => 2 CTA/SM.
// 256 threads, 8x8 micro-tile, packed fma.rn.f32x2.
// ---------------------------------------------------------------------------
#define BM 128
#define BK 64
#define XPAD 132
#define GEMM_SMEM ((D * D + BK * XPAD) * 4)

__global__ void __launch_bounds__(256, 2)
gemm_kernel(const float* __restrict__ X, const float* __restrict__ W,
            float* __restrict__ out, int nrows) {
    extern __shared__ float sm[];
    float* Ws = sm;               // [128][128] row-major (k, c)
    float* Xs = sm + D * D;       // [64][132]  (k, m) transposed, padded

    int tid = threadIdx.x;
    int rowbase = blockIdx.x * BM;

    // load full W
    {
        const float4* Wg = (const float4*)W;
        float4* Ws4 = (float4*)Ws;
#pragma unroll
        for (int i = 0; i < 16; i++) Ws4[tid + i * 256] = Wg[tid + i * 256];
    }

    int tr = tid >> 4, tc = tid & 15;
    int r0 = tr * 8, c0 = tc * 8;

    ull acc[8][4];
#pragma unroll
    for (int i = 0; i < 8; i++)
#pragma unroll
        for (int j = 0; j < 4; j++) acc[i][j] = 0ull;

    const float4* Xg = (const float4*)X;
    float4 z = make_float4(0.f, 0.f, 0.f, 0.f);

    for (int t = 0; t < 2; t++) {
        __syncthreads();   // previous tile compute done (and W load visible on t=0)
        // transposed store: f -> m = f>>4 (row), kq = f&15 (float4 within 64-k tile)
#pragma unroll
        for (int i = 0; i < 8; i++) {
            int f = tid + i * 256;
            int m = f >> 4;
            int kq = f & 15;
            int r = rowbase + m;
            float4 v = (r < nrows) ? Xg[(size_t)r * 32 + t * 16 + kq] : z;
            float* base = Xs + (kq * 4) * XPAD + m;
            base[0]        = v.x;
            base[XPAD]     = v.y;
            base[2 * XPAD] = v.z;
            base[3 * XPAD] = v.w;
        }
        __syncthreads();

#pragma unroll 4
        for (int kk = 0; kk < BK; kk++) {
            int k = t * BK + kk;
            float4 a0 = *(const float4*)(Xs + kk * XPAD + r0);
            float4 a1 = *(const float4*)(Xs + kk * XPAD + r0 + 4);
            ull aa[8] = {pk2(a0.x), pk2(a0.y), pk2(a0.z), pk2(a0.w),
                         pk2(a1.x), pk2(a1.y), pk2(a1.z), pk2(a1.w)};
            ulonglong2 p = *(const ulonglong2*)(Ws + k * D + c0);
            ulonglong2 q = *(const ulonglong2*)(Ws + k * D + c0 + 4);
            ull b[4] = {p.x, p.y, q.x, q.y};
#pragma unroll
            for (int i = 0; i < 8; i++)
#pragma unroll
                for (int j = 0; j < 4; j++) fma2(acc[i][j], aa[i], b[j]);
        }
    }

#pragma unroll
    for (int i = 0; i < 8; i++) {
        int r = rowbase + r0 + i;
        if (r >= nrows) continue;
        float2 v0 = up2(acc[i][0]), v1 = up2(acc[i][1]);
        float2 v2 = up2(acc[i][2]), v3 = up2(acc[i][3]);
        float4* op = (float4*)(out + (size_t)r * D + c0);
        op[0] = make_float4(v0.x, v0.y, v1.x, v1.y);
        op[1] = make_float4(v2.x, v2.y, v3.x, v3.y);
    }
}

// ---------------------------------------------------------------------------
// gather + combine: out[v] = (sum_{s in nbr(v)} P[s]) / max(deg,1) + R[v] + b
// one warp per node; optional ReLU
// ---------------------------------------------------------------------------
template <int RELU>
__global__ void gather_kernel(const float* __restrict__ P,
                              const float* __restrict__ R,
                              const float* __restrict__ bias,
                              float* __restrict__ out, int n) {
    int w = (blockIdx.x * blockDim.x + threadIdx.x) >> 5;
    int lane = threadIdx.x & 31;
    if (w >= n) return;
    int p0 = g_ptr[w], p1 = g_ptr[w + 1];
    const float4* P4 = (const float4*)P;
    float4 acc = make_float4(0.f, 0.f, 0.f, 0.f);
    int j = p0;
    for (; j + 4 <= p1; j += 4) {
        int s0 = g_nbr[j], s1 = g_nbr[j + 1], s2 = g_nbr[j + 2], s3 = g_nbr[j + 3];
        float4 v0 = P4[(size_t)s0 * 32 + lane];
        float4 v1 = P4[(size_t)s1 * 32 + lane];
        float4 v2 = P4[(size_t)s2 * 32 + lane];
        float4 v3 = P4[(size_t)s3 * 32 + lane];
        acc.x += v0.x + v1.x + v2.x + v3.x;
        acc.y += v0.y + v1.y + v2.y + v3.y;
        acc.z += v0.z + v1.z + v2.z + v3.z;
        acc.w += v0.w + v1.w + v2.w + v3.w;
    }
    for (; j < p1; j++) {
        int s = g_nbr[j];
        float4 v = P4[(size_t)s * 32 + lane];
        acc.x += v.x; acc.y += v.y; acc.z += v.z; acc.w += v.w;
    }
    float inv = 1.0f / fmaxf((float)(p1 - p0), 1.0f);
    float4 r = ((const float4*)R)[(size_t)w * 32 + lane];
    float4 b = ((const float4*)bias)[lane];
    float4 res;
    res.x = acc.x * inv + r.x + b.x;
    res.y = acc.y * inv + r.y + b.y;
    res.z = acc.z * inv + r.z + b.z;
    res.w = acc.w * inv + r.w + b.w;
    if (RELU) {
        res.x = fmaxf(res.x, 0.f); res.y = fmaxf(res.y, 0.f);
        res.z = fmaxf(res.z, 0.f); res.w = fmaxf(res.w, 0.f);
    }
    ((float4*)out)[(size_t)w * 32 + lane] = res;
}

// ---------------------------------------------------------------------------
extern "C" void kernel_launch(void* const* d_in, const int* in_sizes, int n_in,
                              void* d_out, int out_size) {
    const float* x   = (const float*)d_in[0];
    const void*  ei  = d_in[1];
    const float* W1l = (const float*)d_in[2];
    const float* b1  = (const float*)d_in[3];
    const float* W1r = (const float*)d_in[4];
    const float* W2l = (const float*)d_in[5];
    const float* b2  = (const float*)d_in[6];
    const float* W2r = (const float*)d_in[7];
    float* out = (float*)d_out;

    int n = in_sizes[0] / D;
    int E = in_sizes[1] / 2;

    float *P, *R, *H;
    cudaGetSymbolAddress((void**)&P, g_P);
    cudaGetSymbolAddress((void**)&R, g_R);
    cudaGetSymbolAddress((void**)&H, g_H);

    cudaFuncSetAttribute(gemm_kernel, cudaFuncAttributeMaxDynamicSharedMemorySize, GEMM_SMEM);

    int G  = (n + BM - 1) / BM;
    int NB = (n + 511) / 512;
    int gatherBlocks = (n * 32 + 255) / 256;

    // CSR build (once, shared by both layers)
    detect_kernel<<<1, 32>>>((const int*)ei, E);
    zero_cnt_kernel<<<256, 256>>>(n);
    count_kernel<<<(E + 255) / 256, 256>>>(ei, E);
    scanA_kernel<<<NB, 512>>>(n);
    scanB_kernel<<<1, 256>>>(NB);
    scanC_kernel<<<(n + 255) / 256, 256>>>(n, E);
    fill_kernel<<<(E + 255) / 256, 256>>>(ei, E);

    // layer 1
    gemm_kernel<<<G, 256, GEMM_SMEM>>>(x, W1l, P, n);
    gemm_kernel<<<G, 256, GEMM_SMEM>>>(x, W1r, R, n);
    gather_kernel<1><<<gatherBlocks, 256>>>(P, R, b1, H, n);

    // layer 2
    gemm_kernel<<<G, 256, GEMM_SMEM>>>(H, W2l, P, n);
    gemm_kernel<<<G, 256, GEMM_SMEM>>>(H, W2r, R, n);
    gather_kernel<0><<<gatherBlocks, 256>>>(P, R, b2, out, n);
}